// round 9
// baseline (speedup 1.0000x reference)
#include <cuda_runtime.h>

#define BB 16
#define LL 2048
#define HH 1024
#define ZZ 512

// Scratch (device globals; no allocation allowed)
__device__ float g_k[BB * HH];          // final @ Wk
__device__ float g_kq[BB * HH];         // Wq @ k
__device__ float g_w[BB * LL];          // RAW masked logits (softmax done in k5)
__device__ float g_part[32 * BB * ZZ];  // partial column sums of latent z
__device__ float g_S2[8 * BB * ZZ];     // split-K partials of S (reduced in k5)

// Intra-launch dependency counters (zero-init at load; reset by k5 each run)
__device__ unsigned g_acnt;             // kA blocks done (target 128)
__device__ unsigned g_bcnt;             // kB blocks done (target 128)
__device__ unsigned g_zcnt[BB];         // z-sum chunks done per batch (target 32)

// ---------------------------------------------------------------------------
// MEGA KERNEL: kA + kB + z-sum + kF + logits in one launch.
// Dependencies resolved by spin gates on lower-block-id stages (acyclic).
//   [0,128)     kA:  k[b,h] = fin[b,:] . Wk[:,h]
//   [128,256)   kB:  kq[b,r] = Wq[r,:] . k[b,:]   (waits kA)
//   [256,768)   kE:  z-sum partials, 67 MB BW backbone
//   [768,896)   kF:  split-K S2 partials            (waits kE per batch)
//   [896,2944)  kC:  raw masked logits, 134 MB BW   (waits kB)
// ---------------------------------------------------------------------------
__global__ void __launch_bounds__(512) k_fused(
    const float* __restrict__ fin, const float* __restrict__ Wk,
    const float* __restrict__ Wq,  const float* __restrict__ Wv,
    const float* __restrict__ zin, const float* __restrict__ enc,
    const int* __restrict__ mask)
{
    __shared__ __align__(16) float smem[8 * HH];   // 32 KB, aliased per stage
    const int blk = blockIdx.x;
    const int t = threadIdx.x;

    if (blk < 128) {
        // ---------------- kA ----------------
        float* sh  = smem;            // [HH]
        float* red = smem + HH;       // [512]
        const int b = blk >> 3;
        const int hof = t & 127;
        const int h = ((blk & 7) << 7) + hof;
        const int cs = t >> 7;
        for (int j = t; j < HH; j += 512) sh[j] = fin[b * HH + j];
        __syncthreads();
        float acc = 0.f;
        const float* wcol = Wk + h;
#pragma unroll 8
        for (int c = cs * 256; c < (cs + 1) * 256; ++c)
            acc += sh[c] * wcol[(size_t)c * HH];
        red[t] = acc;
        __syncthreads();
        if (cs == 0) {
            g_k[b * HH + h] = red[hof] + red[128 + hof] + red[256 + hof] + red[384 + hof];
            __threadfence();
        }
        __syncthreads();
        if (t == 0) atomicAdd(&g_acnt, 1u);

    } else if (blk < 256) {
        // ---------------- kB (waits kA) ----------------
        if (t == 0) {
            while (*(volatile unsigned*)&g_acnt < 128u) {}
            __threadfence();
        }
        __syncthreads();

        float* sk = smem;             // 8 k-vectors, 32 KB
        const int e = blk - 128;
        const int rb = e >> 1;
        const int bg = e & 1;
        for (int j = t; j < 8 * HH; j += 512)
            sk[j] = *(volatile const float*)&g_k[(8 * bg + (j >> 10)) * HH + (j & 1023)];
        __syncthreads();

        const int warp = t >> 5, lane = t & 31;
        const int r = rb * 16 + warp;
        const float4* wrow = (const float4*)(Wq + (size_t)r * HH);
        float acc[8] = {0.f, 0.f, 0.f, 0.f, 0.f, 0.f, 0.f, 0.f};
#pragma unroll 2
        for (int c = lane; c < HH / 4; c += 32) {
            const float4 wv = wrow[c];
#pragma unroll
            for (int j = 0; j < 8; ++j) {
                const float4 kv = ((const float4*)(sk + j * HH))[c];
                acc[j] += wv.x * kv.x + wv.y * kv.y + wv.z * kv.z + wv.w * kv.w;
            }
        }
#pragma unroll
        for (int j = 0; j < 8; ++j) {
            float a = acc[j];
#pragma unroll
            for (int o = 16; o; o >>= 1) a += __shfl_xor_sync(0xffffffffu, a, o);
            if (lane == 0) g_kq[(8 * bg + j) * HH + r] = a;
        }
        if (lane == 0) __threadfence();
        __syncthreads();
        if (t == 0) atomicAdd(&g_bcnt, 1u);

    } else if (blk < 768) {
        // ---------------- kE: z-sum (BW backbone) ----------------
        const int e = blk - 256;               // 0..511
        const int b = e >> 5;
        const int chunk = e & 31;
        const float* base = zin + ((size_t)b * LL + (size_t)chunk * 64) * ZZ + t;
        float acc = 0.f;
#pragma unroll 16
        for (int i = 0; i < 64; ++i) acc += __ldcs(base + (size_t)i * ZZ);
        g_part[(chunk * BB + b) * ZZ + t] = acc;
        __threadfence();
        __syncthreads();
        if (t == 0) atomicAdd(&g_zcnt[b], 1u);

    } else if (blk < 896) {
        // ---------------- kF: split-K S2 (waits kE of batch b) ----------------
        const int e = blk - 768;               // 0..127
        const int b = e >> 3;
        const int slice = e & 7;
        if (t == 0) {
            while (*(volatile unsigned*)&g_zcnt[b] < 32u) {}
            __threadfence();
        }
        __syncthreads();

        float* zs = smem;                       // [64]
        const int cl = t >> 3;                  // 0..63
        const int sub = t & 7;                  // 0..7
        const int c = 64 * slice + cl;
        float a = 0.f;
#pragma unroll
        for (int j = 0; j < 4; ++j)
            a += *(volatile const float*)&g_part[((sub + 8 * j) * BB + b) * ZZ + c];
#pragma unroll
        for (int o = 4; o; o >>= 1) a += __shfl_xor_sync(0xffffffffu, a, o);
        if (sub == 0) zs[cl] = a;
        __syncthreads();

        float s = 0.f;
        const float* wbase = Wv + (size_t)(64 * slice) * ZZ + t;
#pragma unroll 8
        for (int c2 = 0; c2 < 64; ++c2)
            s += zs[c2] * wbase[(size_t)c2 * ZZ];
        g_S2[(slice * BB + b) * ZZ + t] = s;

    } else {
        // ---------------- kC: logits (waits kB) ----------------
        if (t == 0) {
            while (*(volatile unsigned*)&g_bcnt < 128u) {}
            __threadfence();
        }
        __syncthreads();

        const int warp = t >> 5, lane = t & 31;
        const int row = (blk - 896) * 16 + warp;
        const int b = row >> 11;
        const float4* e4 = (const float4*)(enc + (size_t)row * HH);
        const float4* kq4 = (const float4*)(g_kq + b * HH);
        float acc = 0.f;
#pragma unroll
        for (int c = lane; c < HH / 4; c += 32) {
            float4 ev = __ldcs(&e4[c]);
            float4 kv = __ldg(&kq4[c]);
            acc += ev.x * kv.x + ev.y * kv.y + ev.z * kv.z + ev.w * kv.w;
        }
#pragma unroll
        for (int o = 16; o; o >>= 1) acc += __shfl_xor_sync(0xffffffffu, acc, o);
        if (lane == 0) {
            float val = acc * 0.03125f;
            if (mask[row] == 0) val = -1e9f;
            g_w[row] = val;
        }
    }
}

// ---------------------------------------------------------------------------
// k5: fused softmax + S-reduce + streaming writer. 5120 blocks x 256 threads.
// Block 0 also resets the dependency counters for the next graph replay.
// ---------------------------------------------------------------------------
__global__ void __launch_bounds__(256) k5_write(float* __restrict__ out)
{
    __shared__ float red[8];
    __shared__ float s_max, s_inv;
    const int blk = blockIdx.x;
    const int t = threadIdx.x;
    const int warp = t >> 5, lane = t & 31;

    if (blk == 0 && t == 0) {
        g_acnt = 0u;
        g_bcnt = 0u;
#pragma unroll
        for (int i = 0; i < BB; ++i) g_zcnt[i] = 0u;
    }

    const bool is_attn = (blk < 4096);
    const int b = is_attn ? (blk >> 8) : ((blk - 4096) >> 6);

    // ---- softmax stats over this batch's 2048 raw logits ----
    float lg[8];
#pragma unroll
    for (int k = 0; k < 8; ++k) lg[k] = __ldg(&g_w[b * LL + k * 256 + t]);

    float m = lg[0];
#pragma unroll
    for (int k = 1; k < 8; ++k) m = fmaxf(m, lg[k]);
#pragma unroll
    for (int o = 16; o; o >>= 1) m = fmaxf(m, __shfl_xor_sync(0xffffffffu, m, o));
    if (lane == 0) red[warp] = m;
    __syncthreads();
    if (warp == 0 && lane < 8) {
        float v = red[lane];
#pragma unroll
        for (int o = 4; o; o >>= 1) v = fmaxf(v, __shfl_xor_sync(0xffu, v, o));
        if (lane == 0) s_max = v;
    }
    __syncthreads();
    const float M = s_max;

    float s = 0.f;
#pragma unroll
    for (int k = 0; k < 8; ++k) s += __expf(lg[k] - M);   // masked rows -> 0
#pragma unroll
    for (int o = 16; o; o >>= 1) s += __shfl_xor_sync(0xffffffffu, s, o);
    __syncthreads();
    if (lane == 0) red[warp] = s;
    __syncthreads();
    if (warp == 0 && lane < 8) {
        float v = red[lane];
#pragma unroll
        for (int o = 4; o; o >>= 1) v += __shfl_xor_sync(0xffu, v, o);
        if (lane == 0) s_inv = 1.f / v;
    }
    __syncthreads();
    const float inv = s_inv;

    // ---- 16 streaming float4 stores per thread ----
    if (is_attn) {
        const long long base = (long long)b * (LL * LL / 4)
                             + (long long)(blk & 255) * 4096;
        const int rowbase = (int)(base >> 9);
        float4* attn4 = (float4*)(out + (size_t)BB * LL * ZZ);
        float w8[8];
#pragma unroll
        for (int j = 0; j < 8; ++j)
            w8[j] = __expf(__ldg(&g_w[rowbase + j]) - M) * inv;
#pragma unroll
        for (int k = 0; k < 16; ++k) {
            const float wv = w8[k >> 1];
            __stcs(attn4 + base + k * 256 + t, make_float4(wv, wv, wv, wv));
        }
    } else {
        const int e = blk - 4096;
        const long long base = (long long)b * (LL * ZZ / 4)
                             + (long long)(e & 63) * 4096;
        const int rowbase = (int)(base >> 7);
        const int rsub = t >> 7;
        const int col = t & 127;
        const float4* S24 = (const float4*)g_S2;
        float4 sv = make_float4(0.f, 0.f, 0.f, 0.f);
#pragma unroll
        for (int k = 0; k < 8; ++k) {
            const float4 p = __ldg(&S24[(k * BB + b) * (ZZ / 4) + col]);
            sv.x += p.x; sv.y += p.y; sv.z += p.z; sv.w += p.w;
        }
#pragma unroll
        for (int k = 0; k < 16; ++k) {
            const float wv = __expf(__ldg(&g_w[rowbase + 2 * k + rsub]) - M) * inv;
            __stcs((float4*)out + base + k * 256 + t,
                   make_float4(wv * sv.x, wv * sv.y, wv * sv.z, wv * sv.w));
        }
    }
}

// ---------------------------------------------------------------------------
extern "C" void kernel_launch(void* const* d_in, const int* in_sizes, int n_in,
                              void* d_out, int out_size)
{
    const float* enc  = (const float*)d_in[0];
    const float* fin  = (const float*)d_in[1];
    const float* zseq = (const float*)d_in[2];
    const int*   mask = (const int*)  d_in[3];
    const float* Wq   = (const float*)d_in[4];
    const float* Wk   = (const float*)d_in[5];
    const float* Wv   = (const float*)d_in[6];
    float* out = (float*)d_out;

    k_fused<<<2944, 512>>>(fin, Wk, Wq, Wv, zseq, enc, mask);
    k5_write<<<5120, 256>>>(out);
}